// round 2
// baseline (speedup 1.0000x reference)
#include <cuda_runtime.h>
#include <cuda_bf16.h>
#include <math.h>

#define DD 256
#define SS 22
#define NAC 20
#define NTOK 768
#define NWIN 7
#define BATCH 32
#define BWIN 224
#define MBIG 172032
#define MGRU 4928
#define MSO  4480
#define SLOTS_OUT_ELEMS 1146880  // 32*7*20*256

__device__ float g_pe[NTOK * DD];
__device__ float g_buf0[MBIG * DD];
__device__ float g_buf1[MBIG * DD];
__device__ float g_buf2[MBIG * DD];
__device__ float g_qs[SS * DD];
__device__ float g_hg[SS * 768];
__device__ float g_upd[MGRU * DD];
__device__ float g_xg[MGRU * 768];
__device__ float g_so[MSO * DD];
__device__ float g_soln[MSO * DD];
__device__ float g_t2[MSO * DD];
__device__ float g_t3[MSO * DD];

__device__ __forceinline__ unsigned long long pk(float x, float y) {
    unsigned long long r;
    asm("mov.b64 %0, {%1,%2};" : "=l"(r) : "f"(x), "f"(y));
    return r;
}
__device__ __forceinline__ void upk(unsigned long long v, float& x, float& y) {
    asm("mov.b64 {%0,%1}, %2;" : "=f"(x), "=f"(y) : "l"(v));
}
__device__ __forceinline__ unsigned long long fma2(unsigned long long a,
                                                   unsigned long long b,
                                                   unsigned long long c) {
    unsigned long long d;
    asm("fma.rn.f32x2 %0, %1, %2, %3;" : "=l"(d) : "l"(a), "l"(b), "l"(c));
    return d;
}

__device__ __forceinline__ float blockSum(float v, float* s) {
    int tid = threadIdx.x;
#pragma unroll
    for (int o = 16; o > 0; o >>= 1) v += __shfl_down_sync(0xffffffffu, v, o);
    if ((tid & 31) == 0) s[tid >> 5] = v;
    __syncthreads();
    float r = (tid < (blockDim.x >> 5)) ? s[tid] : 0.f;
    if (tid < 32) {
#pragma unroll
        for (int o = 4; o > 0; o >>= 1) r += __shfl_down_sync(0xffffffffu, r, o);
    }
    if (tid == 0) s[0] = r;
    __syncthreads();
    r = s[0];
    __syncthreads();
    return r;
}

// K0: positional embedding
__global__ void k_pe(const float* __restrict__ pe_w, const float* __restrict__ pe_b) {
    int p = blockIdx.x, c = threadIdx.x;
    int t = p / 192, rem = p % 192, y = rem / 24, x = rem % 24;
    float g0 = t * (1.f / 3.f), g1 = y * (1.f / 7.f), g2 = x * (1.f / 23.f);
    const float* wr = pe_w + c * 6;
    g_pe[p * DD + c] = pe_b[c] + wr[0] * g0 + wr[1] * g1 + wr[2] * g2
        + wr[3] * (1.f - g0) + wr[4] * (1.f - g1) + wr[5] * (1.f - g2);
}

// K1: gather window + pe + LayerNorm -> g_buf0
__global__ void k_winln(const float* __restrict__ inp,
                        const float* __restrict__ gam,
                        const float* __restrict__ bet) {
    __shared__ float red[32];
    int m = blockIdx.x, c = threadIdx.x;
    int wiB = m / NTOK, p = m % NTOK;
    int wi = wiB / BATCH, bb = wiB % BATCH;
    int t = p / 192, rem = p % 192;
    int f = 2 * wi + t;
    float x = inp[((size_t)(bb * 16 + f) * 192 + rem) * DD + c] + g_pe[p * DD + c];
    float mean = blockSum(x, red) * (1.f / 256.f);
    float d0 = x - mean;
    float var = blockSum(d0 * d0, red) * (1.f / 256.f);
    g_buf0[(size_t)m * DD + c] = d0 * rsqrtf(var + 1e-5f) * gam[c] + bet[c];
}

// generic LayerNorm row kernel
__global__ void k_ln(const float* __restrict__ src, float* __restrict__ dst,
                     const float* __restrict__ gam, const float* __restrict__ bet) {
    __shared__ float red[32];
    int m = blockIdx.x, c = threadIdx.x;
    float x = src[(size_t)m * DD + c];
    float mean = blockSum(x, red) * (1.f / 256.f);
    float d0 = x - mean;
    float var = blockSum(d0 * d0, red) * (1.f / 256.f);
    dst[(size_t)m * DD + c] = d0 * rsqrtf(var + 1e-5f) * gam[c] + bet[c];
}

// GEMM: C[M,N] = A[M,256] @ W[N,256]^T + bias (optional ReLU)
// 128x64 tile, BK=16, 256 threads, 8x4 per-thread via packed f32x2
template <bool RELU>
__global__ void __launch_bounds__(256) k_gemm(const float* __restrict__ A,
                                              const float* __restrict__ W,
                                              const float* __restrict__ bias,
                                              float* __restrict__ C,
                                              int M, int N) {
    __shared__ float As[16][132];
    __shared__ float Bs[16][68];
    int tid = threadIdx.x;
    int m0 = blockIdx.x * 128, n0 = blockIdx.y * 64;
    int tx = tid & 15, ty = tid >> 4;
    int arow = m0 + (tid >> 1), acol = (tid & 1) * 8;
    int brow = n0 + (tid >> 2), bcol = (tid & 3) * 4;
    const bool aval = arow < M;

    unsigned long long cp[4][4];
#pragma unroll
    for (int i = 0; i < 4; i++)
#pragma unroll
        for (int j = 0; j < 4; j++) cp[i][j] = 0ULL;

    for (int k0 = 0; k0 < 256; k0 += 16) {
        float4 av0 = make_float4(0.f, 0.f, 0.f, 0.f), av1 = av0;
        if (aval) {
            av0 = *(const float4*)(A + (size_t)arow * 256 + k0 + acol);
            av1 = *(const float4*)(A + (size_t)arow * 256 + k0 + acol + 4);
        }
        float4 bv = *(const float4*)(W + (size_t)brow * 256 + k0 + bcol);
        int ar = tid >> 1;
        As[acol + 0][ar] = av0.x; As[acol + 1][ar] = av0.y;
        As[acol + 2][ar] = av0.z; As[acol + 3][ar] = av0.w;
        As[acol + 4][ar] = av1.x; As[acol + 5][ar] = av1.y;
        As[acol + 6][ar] = av1.z; As[acol + 7][ar] = av1.w;
        int br = tid >> 2;
        Bs[bcol + 0][br] = bv.x; Bs[bcol + 1][br] = bv.y;
        Bs[bcol + 2][br] = bv.z; Bs[bcol + 3][br] = bv.w;
        __syncthreads();
#pragma unroll
        for (int kk = 0; kk < 16; kk++) {
            ulonglong2 la = *(const ulonglong2*)&As[kk][ty * 8];
            ulonglong2 lb = *(const ulonglong2*)&As[kk][ty * 8 + 4];
            float4 bq = *(const float4*)&Bs[kk][tx * 4];
            unsigned long long am[4] = {la.x, la.y, lb.x, lb.y};
            unsigned long long bs[4] = {pk(bq.x, bq.x), pk(bq.y, bq.y),
                                        pk(bq.z, bq.z), pk(bq.w, bq.w)};
#pragma unroll
            for (int mp = 0; mp < 4; mp++)
#pragma unroll
                for (int n = 0; n < 4; n++)
                    cp[mp][n] = fma2(am[mp], bs[n], cp[mp][n]);
        }
        __syncthreads();
    }

    float4 b4 = *(const float4*)(bias + n0 + tx * 4);
#pragma unroll
    for (int mp = 0; mp < 4; mp++) {
        float lo[4], hi[4];
#pragma unroll
        for (int n = 0; n < 4; n++) upk(cp[mp][n], lo[n], hi[n]);
        float4 o0 = make_float4(lo[0] + b4.x, lo[1] + b4.y, lo[2] + b4.z, lo[3] + b4.w);
        float4 o1 = make_float4(hi[0] + b4.x, hi[1] + b4.y, hi[2] + b4.z, hi[3] + b4.w);
        if (RELU) {
            o0.x = fmaxf(o0.x, 0.f); o0.y = fmaxf(o0.y, 0.f);
            o0.z = fmaxf(o0.z, 0.f); o0.w = fmaxf(o0.w, 0.f);
            o1.x = fmaxf(o1.x, 0.f); o1.y = fmaxf(o1.y, 0.f);
            o1.z = fmaxf(o1.z, 0.f); o1.w = fmaxf(o1.w, 0.f);
        }
        int r0 = m0 + ty * 8 + mp * 2;
        if (r0 < M)     *(float4*)(C + (size_t)r0 * N + n0 + tx * 4) = o0;
        if (r0 + 1 < M) *(float4*)(C + (size_t)(r0 + 1) * N + n0 + tx * 4) = o1;
    }
}

// q = LN_ns(slots)@q_w^T + q_b ; hg = slots@gru_wh^T + gru_bh (22 rows)
__global__ void k_small(const float* __restrict__ slots,
                        const float* __restrict__ nsg, const float* __restrict__ nsb,
                        const float* __restrict__ qw, const float* __restrict__ qb,
                        const float* __restrict__ wh, const float* __restrict__ bh) {
    __shared__ float red[32];
    __shared__ float sraw[DD];
    __shared__ float sln[DD];
    int i = blockIdx.x, c = threadIdx.x;
    float x = slots[i * DD + c];
    sraw[c] = x;
    float mean = blockSum(x, red) * (1.f / 256.f);
    float d0 = x - mean;
    float var = blockSum(d0 * d0, red) * (1.f / 256.f);
    sln[c] = d0 * rsqrtf(var + 1e-5f) * nsg[c] + nsb[c];
    __syncthreads();
    float acc = qb[c];
    const float* wr = qw + (size_t)c * 256;
#pragma unroll 8
    for (int k = 0; k < 256; k++) acc += sln[k] * wr[k];
    g_qs[i * DD + c] = acc;
#pragma unroll
    for (int j = 0; j < 3; j++) {
        int u = j * 256 + c;
        float a = bh[u];
        const float* hr = wh + (size_t)u * 256;
#pragma unroll 8
        for (int k = 0; k < 256; k++) a += sraw[k] * hr[k];
        g_hg[i * 768 + u] = a;
    }
}

__device__ __forceinline__ void softmax_store(const unsigned long long* d,
                                              float* __restrict__ dst, int j) {
    float v[SS];
#pragma unroll
    for (int ip = 0; ip < 11; ip++) {
        float a, b;
        upk(d[ip], a, b);
        v[2 * ip] = a * 0.0625f;
        v[2 * ip + 1] = b * 0.0625f;
    }
    float mx = v[0];
#pragma unroll
    for (int i = 1; i < SS; i++) mx = fmaxf(mx, v[i]);
    float s = 0.f;
#pragma unroll
    for (int i = 0; i < SS; i++) { v[i] = __expf(v[i] - mx); s += v[i]; }
    float inv = 1.f / s;
#pragma unroll
    for (int i = 0; i < SS; i++) dst[i * NTOK + j] = v[i] * inv + 1e-8f;
}

// fused dots + softmax-over-slots + EPS -> attn_ori (written to output layout)
__global__ void __launch_bounds__(384) k_attn(float* __restrict__ out_attn,
                                              const float* __restrict__ kk) {
    __shared__ unsigned long long q2[11 * 256];
    __shared__ float ks[8][768];
    int bB = blockIdx.x, tid = threadIdx.x;
    for (int idx = tid; idx < 11 * 256; idx += 384) {
        int ip = idx >> 8, k = idx & 255;
        q2[idx] = pk(g_qs[(2 * ip) * DD + k], g_qs[(2 * ip + 1) * DD + k]);
    }
    unsigned long long da[11], db[11];
#pragma unroll
    for (int ip = 0; ip < 11; ip++) { da[ip] = 0ULL; db[ip] = 0ULL; }
    size_t rowbase = (size_t)bB * NTOK;
    for (int kc = 0; kc < 256; kc += 8) {
#pragma unroll
        for (int rr = 0; rr < 2; rr++) {
            int r = tid + rr * 384;
            const float4* src = (const float4*)(kk + (rowbase + r) * 256 + kc);
            float4 v0 = src[0], v1 = src[1];
            ks[0][r] = v0.x; ks[1][r] = v0.y; ks[2][r] = v0.z; ks[3][r] = v0.w;
            ks[4][r] = v1.x; ks[5][r] = v1.y; ks[6][r] = v1.z; ks[7][r] = v1.w;
        }
        __syncthreads();
#pragma unroll
        for (int kl = 0; kl < 8; kl++) {
            int k = kc + kl;
            float kv0 = ks[kl][tid], kv1 = ks[kl][tid + 384];
            unsigned long long s0 = pk(kv0, kv0), s1 = pk(kv1, kv1);
#pragma unroll
            for (int ip = 0; ip < 11; ip++) {
                unsigned long long qv = q2[ip * 256 + k];
                da[ip] = fma2(qv, s0, da[ip]);
                db[ip] = fma2(qv, s1, db[ip]);
            }
        }
        __syncthreads();
    }
    int wi = bB / BATCH, bb = bB % BATCH;
    float* dst = out_attn + ((size_t)(bb * NWIN + wi)) * SS * NTOK;
    softmax_store(da, dst, tid);
    softmax_store(db, dst, tid + 384);
}

// L1 renorm over tokens + weighted update: upd = attn @ vv
__global__ void __launch_bounds__(256) k_upd(const float* __restrict__ attn,
                                             const float* __restrict__ vv) {
    __shared__ float red[32];
    __shared__ float sinv[SS];
    __shared__ unsigned long long at2[11 * 64];
    int bB = blockIdx.x, tid = threadIdx.x;
    int wi = bB / BATCH, bb = bB % BATCH;
    const float* ab = attn + ((size_t)(bb * NWIN + wi)) * SS * NTOK;
    for (int i = 0; i < SS; i++) {
        float p = 0.f;
        for (int j = tid; j < NTOK; j += 256) p += ab[i * NTOK + j];
        float s = blockSum(p, red);
        if (tid == 0) sinv[i] = 1.f / s;
    }
    __syncthreads();
    unsigned long long acc[11];
#pragma unroll
    for (int ip = 0; ip < 11; ip++) acc[ip] = 0ULL;
    for (int j0 = 0; j0 < NTOK; j0 += 64) {
        for (int idx = tid; idx < 11 * 64; idx += 256) {
            int ip = idx >> 6, jj = idx & 63;
            at2[idx] = pk(ab[(2 * ip) * NTOK + j0 + jj],
                          ab[(2 * ip + 1) * NTOK + j0 + jj]);
        }
        __syncthreads();
        const float* vp = vv + ((size_t)bB * NTOK + j0) * 256 + tid;
#pragma unroll 4
        for (int jj = 0; jj < 64; jj++) {
            float v = vp[(size_t)jj * 256];
            unsigned long long sv = pk(v, v);
#pragma unroll
            for (int ip = 0; ip < 11; ip++)
                acc[ip] = fma2(at2[ip * 64 + jj], sv, acc[ip]);
        }
        __syncthreads();
    }
#pragma unroll
    for (int ip = 0; ip < 11; ip++) {
        float u0, u1;
        upk(acc[ip], u0, u1);
        g_upd[((size_t)bB * SS + 2 * ip) * DD + tid] = u0 * sinv[2 * ip];
        g_upd[((size_t)bB * SS + 2 * ip + 1) * DD + tid] = u1 * sinv[2 * ip + 1];
    }
}

// GRU gates + new hidden, keep first 20 slots
__global__ void k_gate(const float* __restrict__ slots) {
    int m = blockIdx.x, c = threadIdx.x;
    int Bi = m / NAC, i = m % NAC;
    size_t row = (size_t)Bi * SS + i;
    float ir = g_xg[row * 768 + c];
    float iz = g_xg[row * 768 + 256 + c];
    float in_ = g_xg[row * 768 + 512 + c];
    float hr = g_hg[i * 768 + c];
    float hz = g_hg[i * 768 + 256 + c];
    float hn = g_hg[i * 768 + 512 + c];
    float h = slots[i * DD + c];
    float r = 1.f / (1.f + __expf(-(ir + hr)));
    float z = 1.f / (1.f + __expf(-(iz + hz)));
    float n = tanhf(in_ + r * hn);
    g_so[(size_t)m * DD + c] = (1.f - z) * n + z * h;
}

// residual add + permute to (b,7,20,256)
__global__ void k_final(float* __restrict__ out) {
    int m = blockIdx.x, c = threadIdx.x;
    int Bi = m / NAC, sl = m % NAC;
    int wi = Bi / BATCH, bb = Bi % BATCH;
    out[(((size_t)bb * NWIN + wi) * NAC + sl) * DD + c] =
        g_so[(size_t)m * DD + c] + g_t3[(size_t)m * DD + c];
}

extern "C" void kernel_launch(void* const* d_in, const int* in_sizes, int n_in,
                              void* d_out, int out_size) {
    const float* inputs = (const float*)d_in[0];
    const float* slots  = (const float*)d_in[1];
    const float* pe_w   = (const float*)d_in[2];
    const float* pe_b   = (const float*)d_in[3];
    const float* LN_g   = (const float*)d_in[4];
    const float* LN_b   = (const float*)d_in[5];
    const float* ni_g   = (const float*)d_in[6];
    const float* ni_b   = (const float*)d_in[7];
    const float* ns_g   = (const float*)d_in[8];
    const float* ns_b   = (const float*)d_in[9];
    const float* npf_g  = (const float*)d_in[10];
    const float* npf_b  = (const float*)d_in[11];
    const float* FC1_w  = (const float*)d_in[12];
    const float* FC1_b  = (const float*)d_in[13];
    const float* FC2_w  = (const float*)d_in[14];
    const float* FC2_b  = (const float*)d_in[15];
    const float* q_w    = (const float*)d_in[16];
    const float* q_b    = (const float*)d_in[17];
    const float* k_w    = (const float*)d_in[18];
    const float* k_b    = (const float*)d_in[19];
    const float* v_w    = (const float*)d_in[20];
    const float* v_b    = (const float*)d_in[21];
    const float* ff1_w  = (const float*)d_in[22];
    const float* ff1_b  = (const float*)d_in[23];
    const float* ff2_w  = (const float*)d_in[24];
    const float* ff2_b  = (const float*)d_in[25];
    const float* gru_wi = (const float*)d_in[26];
    const float* gru_wh = (const float*)d_in[27];
    const float* gru_bi = (const float*)d_in[28];
    const float* gru_bh = (const float*)d_in[29];

    float* out = (float*)d_out;
    float* out_attn = out + SLOTS_OUT_ELEMS;

    float *b0, *b1, *b2, *qs_, *hg_, *upd_, *xg_, *so_, *soln_, *t2_, *t3_;
    cudaGetSymbolAddress((void**)&b0, g_buf0);
    cudaGetSymbolAddress((void**)&b1, g_buf1);
    cudaGetSymbolAddress((void**)&b2, g_buf2);
    cudaGetSymbolAddress((void**)&upd_, g_upd);
    cudaGetSymbolAddress((void**)&xg_, g_xg);
    cudaGetSymbolAddress((void**)&so_, g_so);
    cudaGetSymbolAddress((void**)&soln_, g_soln);
    cudaGetSymbolAddress((void**)&t2_, g_t2);
    cudaGetSymbolAddress((void**)&t3_, g_t3);
    (void)qs_; (void)hg_;

    // positional embedding + gather + LN
    k_pe<<<NTOK, 256>>>(pe_w, pe_b);
    k_winln<<<MBIG, 256>>>(inputs, LN_g, LN_b);

    // MLP: FC1 (relu) -> FC2
    dim3 gBig(MBIG / 128, 4);
    k_gemm<true><<<gBig, 256>>>(b0, FC1_w, FC1_b, b1, MBIG, 256);
    k_gemm<false><<<gBig, 256>>>(b1, FC2_w, FC2_b, b2, MBIG, 256);

    // norm_input, K and V projections
    k_ln<<<MBIG, 256>>>(b2, b0, ni_g, ni_b);
    k_gemm<false><<<gBig, 256>>>(b0, k_w, k_b, b1, MBIG, 256);  // kk
    k_gemm<false><<<gBig, 256>>>(b0, v_w, v_b, b2, MBIG, 256);  // vv

    // batch-invariant q and hidden gates
    k_small<<<SS, 256>>>(slots, ns_g, ns_b, q_w, q_b, gru_wh, gru_bh);

    // dots + softmax-over-slots + EPS  (writes attns output directly)
    k_attn<<<BWIN, 384>>>(out_attn, b1);

    // renorm + weighted update
    k_upd<<<BWIN, 256>>>(out_attn, b2);

    // GRU input gates GEMM: (4928x256)@(768x256)^T
    dim3 gGru((MGRU + 127) / 128, 12);
    k_gemm<false><<<gGru, 256>>>(upd_, gru_wi, gru_bi, xg_, MGRU, 768);

    // gates -> slots (first 20)
    k_gate<<<MSO, 256>>>(slots);

    // residual MLP
    k_ln<<<MSO, 256>>>(so_, soln_, npf_g, npf_b);
    dim3 gSo(MSO / 128, 4);
    k_gemm<true><<<gSo, 256>>>(soln_, ff1_w, ff1_b, t2_, MSO, 256);
    k_gemm<false><<<gSo, 256>>>(t2_, ff2_w, ff2_b, t3_, MSO, 256);

    // residual + permute into slots output
    k_final<<<MSO, 256>>>(out);
}

// round 4
// speedup vs baseline: 1.4595x; 1.4595x over previous
#include <cuda_runtime.h>
#include <cuda_bf16.h>
#include <math.h>
#include <stdint.h>

#define DD 256
#define SS 22
#define NAC 20
#define NTOK 768
#define NWIN 7
#define BATCH 32
#define BWIN 224
#define MBIG 172032
#define MGRU 4928
#define MSO  4480
#define SLOTS_OUT_ELEMS 1146880  // 32*7*20*256

__device__ float g_pe[NTOK * DD];
__device__ float g_buf0[MBIG * DD];
__device__ float g_buf1[MBIG * DD];
__device__ float g_buf2[MBIG * DD];
__device__ float g_qs[SS * DD];
__device__ float g_hg[SS * 768];
__device__ float g_upd[MGRU * DD];
__device__ float g_xg[MGRU * 768];
__device__ float g_so[MSO * DD];
__device__ float g_soln[MSO * DD];
__device__ float g_t2[MSO * DD];
__device__ float g_t3[MSO * DD];
// pre-split weights (hi/lo bf16): FC1, FC2, k, v
__device__ __nv_bfloat16 g_w1h[65536], g_w1l[65536];
__device__ __nv_bfloat16 g_w2h[65536], g_w2l[65536];
__device__ __nv_bfloat16 g_wkh[65536], g_wkl[65536];
__device__ __nv_bfloat16 g_wvh[65536], g_wvl[65536];

// ---------------- helpers ----------------
__device__ __forceinline__ uint32_t smem_u32(const void* p) {
    uint32_t a;
    asm("{ .reg .u64 t; cvta.to.shared.u64 t, %1; cvt.u32.u64 %0, t; }" : "=r"(a) : "l"(p));
    return a;
}
__device__ __forceinline__ unsigned long long pk(float x, float y) {
    unsigned long long r;
    asm("mov.b64 %0, {%1,%2};" : "=l"(r) : "f"(x), "f"(y));
    return r;
}
__device__ __forceinline__ void upk(unsigned long long v, float& x, float& y) {
    asm("mov.b64 {%0,%1}, %2;" : "=f"(x), "=f"(y) : "l"(v));
}
__device__ __forceinline__ unsigned long long fma2(unsigned long long a,
                                                   unsigned long long b,
                                                   unsigned long long c) {
    unsigned long long d;
    asm("fma.rn.f32x2 %0, %1, %2, %3;" : "=l"(d) : "l"(a), "l"(b), "l"(c));
    return d;
}
__device__ __forceinline__ uint32_t bfpack(float a, float b) {
    __nv_bfloat162 t = __floats2bfloat162_rn(a, b);
    return *reinterpret_cast<uint32_t*>(&t);
}
__device__ __forceinline__ void ldsm4(uint32_t* r, uint32_t addr) {
    asm volatile("ldmatrix.sync.aligned.m8n8.x4.shared.b16 {%0,%1,%2,%3}, [%4];"
        : "=r"(r[0]), "=r"(r[1]), "=r"(r[2]), "=r"(r[3]) : "r"(addr));
}
__device__ __forceinline__ void mma16816(float* d, const uint32_t* a,
                                         uint32_t b0, uint32_t b1) {
    asm volatile(
        "mma.sync.aligned.m16n8k16.row.col.f32.bf16.bf16.f32 "
        "{%0,%1,%2,%3}, {%4,%5,%6,%7}, {%8,%9}, {%0,%1,%2,%3};"
        : "+f"(d[0]), "+f"(d[1]), "+f"(d[2]), "+f"(d[3])
        : "r"(a[0]), "r"(a[1]), "r"(a[2]), "r"(a[3]), "r"(b0), "r"(b1));
}

__device__ __forceinline__ float blockSum(float v, float* s) {
    int tid = threadIdx.x;
#pragma unroll
    for (int o = 16; o > 0; o >>= 1) v += __shfl_down_sync(0xffffffffu, v, o);
    if ((tid & 31) == 0) s[tid >> 5] = v;
    __syncthreads();
    float r = (tid < (blockDim.x >> 5)) ? s[tid] : 0.f;
    if (tid < 32) {
#pragma unroll
        for (int o = 4; o > 0; o >>= 1) r += __shfl_down_sync(0xffffffffu, r, o);
    }
    if (tid == 0) s[0] = r;
    __syncthreads();
    r = s[0];
    __syncthreads();
    return r;
}

// ---------------- small kernels ----------------
__global__ void k_pe(const float* __restrict__ pe_w, const float* __restrict__ pe_b) {
    int p = blockIdx.x, c = threadIdx.x;
    int t = p / 192, rem = p % 192, y = rem / 24, x = rem % 24;
    float g0 = t * (1.f / 3.f), g1 = y * (1.f / 7.f), g2 = x * (1.f / 23.f);
    const float* wr = pe_w + c * 6;
    g_pe[p * DD + c] = pe_b[c] + wr[0] * g0 + wr[1] * g1 + wr[2] * g2
        + wr[3] * (1.f - g0) + wr[4] * (1.f - g1) + wr[5] * (1.f - g2);
}

__global__ void k_winln(const float* __restrict__ inp,
                        const float* __restrict__ gam,
                        const float* __restrict__ bet) {
    __shared__ float red[32];
    int m = blockIdx.x, c = threadIdx.x;
    int wiB = m / NTOK, p = m % NTOK;
    int wi = wiB / BATCH, bb = wiB % BATCH;
    int t = p / 192, rem = p % 192;
    int f = 2 * wi + t;
    float x = inp[((size_t)(bb * 16 + f) * 192 + rem) * DD + c] + g_pe[p * DD + c];
    float mean = blockSum(x, red) * (1.f / 256.f);
    float d0 = x - mean;
    float var = blockSum(d0 * d0, red) * (1.f / 256.f);
    g_buf0[(size_t)m * DD + c] = d0 * rsqrtf(var + 1e-5f) * gam[c] + bet[c];
}

__global__ void k_ln(const float* __restrict__ src, float* __restrict__ dst,
                     const float* __restrict__ gam, const float* __restrict__ bet) {
    __shared__ float red[32];
    int m = blockIdx.x, c = threadIdx.x;
    float x = src[(size_t)m * DD + c];
    float mean = blockSum(x, red) * (1.f / 256.f);
    float d0 = x - mean;
    float var = blockSum(d0 * d0, red) * (1.f / 256.f);
    dst[(size_t)m * DD + c] = d0 * rsqrtf(var + 1e-5f) * gam[c] + bet[c];
}

__global__ void k_split(const float* __restrict__ w, __nv_bfloat16* __restrict__ h,
                        __nv_bfloat16* __restrict__ l, int n) {
    int i = blockIdx.x * 256 + threadIdx.x;
    if (i < n) {
        float x = w[i];
        __nv_bfloat16 hh = __float2bfloat16(x);
        h[i] = hh;
        l[i] = __float2bfloat16(x - __bfloat162float(hh));
    }
}

// ---------------- mma.sync split-bf16 GEMM ----------------
// C[M,256] = A[M,256] @ W[256,256]^T + bias (optional ReLU), M % 128 == 0
// CTA 128x128, BK=64, 4 chunks, warp tile 32x64 (8 warps: 4 in M x 2 in N).
// smem: Ah/Al 128x(64+8) bf16 + Bh/Bl 128x(64+8) bf16 = 73728 B
#define MM_SMEM 73728
#define ROWB 144  // (64+8) bf16 row stride in bytes

template <bool RELU>
__global__ void __launch_bounds__(256) k_mma(const float* __restrict__ A,
                                             const __nv_bfloat16* __restrict__ Wh,
                                             const __nv_bfloat16* __restrict__ Wl,
                                             const float* __restrict__ bias,
                                             float* __restrict__ C, int M) {
    extern __shared__ char sm[];
    const uint32_t AhO = 0, AlO = 18432, BhO = 36864, BlO = 55296;
    int tid = threadIdx.x, lane = tid & 31, wid = tid >> 5;
    int m0 = blockIdx.x * 128, n0 = blockIdx.y * 128;
    int mw = wid & 3, nw = wid >> 2;
    uint32_t sb = smem_u32(sm);

    float acc[2][8][4];
#pragma unroll
    for (int i = 0; i < 2; i++)
#pragma unroll
        for (int j = 0; j < 8; j++)
#pragma unroll
            for (int k = 0; k < 4; k++) acc[i][j][k] = 0.f;

    for (int ch = 0; ch < 4; ch++) {
        int k0 = ch * 64;
        // load A chunk: 128 rows x 64 fp32 -> hi/lo bf16
#pragma unroll
        for (int i = 0; i < 8; i++) {
            int idx = tid + i * 256;
            int row = idx >> 4, cg = idx & 15;
            float4 v = *reinterpret_cast<const float4*>(
                A + (size_t)(m0 + row) * 256 + k0 + cg * 4);
            __nv_bfloat16 hx = __float2bfloat16(v.x);
            __nv_bfloat16 hy = __float2bfloat16(v.y);
            __nv_bfloat16 hz = __float2bfloat16(v.z);
            __nv_bfloat16 hw = __float2bfloat16(v.w);
            uint2 H, L;
            H.x = bfpack(__bfloat162float(hx), 0.f);  // placeholder, fixed below
            // pack hi
            {
                __nv_bfloat162 p0; p0.x = hx; p0.y = hy;
                __nv_bfloat162 p1; p1.x = hz; p1.y = hw;
                H.x = *reinterpret_cast<uint32_t*>(&p0);
                H.y = *reinterpret_cast<uint32_t*>(&p1);
            }
            L.x = bfpack(v.x - __bfloat162float(hx), v.y - __bfloat162float(hy));
            L.y = bfpack(v.z - __bfloat162float(hz), v.w - __bfloat162float(hw));
            uint32_t off = (uint32_t)row * ROWB + cg * 8;
            *reinterpret_cast<uint2*>(sm + AhO + off) = H;
            *reinterpret_cast<uint2*>(sm + AlO + off) = L;
        }
        // load B chunk: 128 n-rows x 64 k bf16 (hi & lo)
#pragma unroll
        for (int i = 0; i < 4; i++) {
            int idx = tid + i * 256;
            int row = idx >> 3, g = idx & 7;
            size_t gb = (size_t)(n0 + row) * 256 + k0 + g * 8;
            uint4 H = *reinterpret_cast<const uint4*>(Wh + gb);
            uint4 L = *reinterpret_cast<const uint4*>(Wl + gb);
            uint32_t off = (uint32_t)row * ROWB + g * 16;
            *reinterpret_cast<uint4*>(sm + BhO + off) = H;
            *reinterpret_cast<uint4*>(sm + BlO + off) = L;
        }
        __syncthreads();
#pragma unroll
        for (int ks = 0; ks < 4; ks++) {
            int k = ks * 16;
            uint32_t ah[2][4], al[2][4];
#pragma unroll
            for (int mt = 0; mt < 2; mt++) {
                uint32_t addr = sb + AhO
                    + (uint32_t)(mw * 32 + mt * 16 + (lane & 15)) * ROWB
                    + (uint32_t)(k + (lane >> 4) * 8) * 2;
                ldsm4(ah[mt], addr);
                ldsm4(al[mt], addr + (AlO - AhO));
            }
#pragma unroll
            for (int p = 0; p < 4; p++) {
                uint32_t baddr = sb + BhO
                    + (uint32_t)(nw * 64 + p * 16 + (lane & 15)) * ROWB
                    + (uint32_t)(k + (lane >> 4) * 8) * 2;
                uint32_t bh[4], bl[4];
                ldsm4(bh, baddr);
                ldsm4(bl, baddr + (BlO - BhO));
#pragma unroll
                for (int mt = 0; mt < 2; mt++) {
                    // nt = 2p: regs {bh[0], bh[2]}
                    mma16816(acc[mt][2 * p], ah[mt], bh[0], bh[2]);
                    mma16816(acc[mt][2 * p], ah[mt], bl[0], bl[2]);
                    mma16816(acc[mt][2 * p], al[mt], bh[0], bh[2]);
                    // nt = 2p+1: regs {bh[1], bh[3]}
                    mma16816(acc[mt][2 * p + 1], ah[mt], bh[1], bh[3]);
                    mma16816(acc[mt][2 * p + 1], ah[mt], bl[1], bl[3]);
                    mma16816(acc[mt][2 * p + 1], al[mt], bh[1], bh[3]);
                }
            }
        }
        __syncthreads();
    }

    // epilogue
#pragma unroll
    for (int nt = 0; nt < 8; nt++) {
        int col = n0 + nw * 64 + nt * 8 + (lane & 3) * 2;
        float bx = bias[col], by = bias[col + 1];
#pragma unroll
        for (int mt = 0; mt < 2; mt++) {
            int row = m0 + mw * 32 + mt * 16 + (lane >> 2);
            float* a = acc[mt][nt];
            float2 o0 = make_float2(a[0] + bx, a[1] + by);
            float2 o1 = make_float2(a[2] + bx, a[3] + by);
            if (RELU) {
                o0.x = fmaxf(o0.x, 0.f); o0.y = fmaxf(o0.y, 0.f);
                o1.x = fmaxf(o1.x, 0.f); o1.y = fmaxf(o1.y, 0.f);
            }
            *reinterpret_cast<float2*>(C + (size_t)row * 256 + col) = o0;
            *reinterpret_cast<float2*>(C + (size_t)(row + 8) * 256 + col) = o1;
        }
    }
}

// ---------------- FFMA2 GEMM (gru / ff) ----------------
template <bool RELU>
__global__ void __launch_bounds__(256) k_gemm(const float* __restrict__ A,
                                              const float* __restrict__ W,
                                              const float* __restrict__ bias,
                                              float* __restrict__ C,
                                              int M, int N) {
    __shared__ float As[16][132];
    __shared__ float Bs[16][68];
    int tid = threadIdx.x;
    int m0 = blockIdx.x * 128, n0 = blockIdx.y * 64;
    int tx = tid & 15, ty = tid >> 4;
    int arow = m0 + (tid >> 1), acol = (tid & 1) * 8;
    int brow = n0 + (tid >> 2), bcol = (tid & 3) * 4;
    const bool aval = arow < M;

    unsigned long long cp[4][4];
#pragma unroll
    for (int i = 0; i < 4; i++)
#pragma unroll
        for (int j = 0; j < 4; j++) cp[i][j] = 0ULL;

    for (int k0 = 0; k0 < 256; k0 += 16) {
        float4 av0 = make_float4(0.f, 0.f, 0.f, 0.f), av1 = av0;
        if (aval) {
            av0 = *(const float4*)(A + (size_t)arow * 256 + k0 + acol);
            av1 = *(const float4*)(A + (size_t)arow * 256 + k0 + acol + 4);
        }
        float4 bv = *(const float4*)(W + (size_t)brow * 256 + k0 + bcol);
        int ar = tid >> 1;
        As[acol + 0][ar] = av0.x; As[acol + 1][ar] = av0.y;
        As[acol + 2][ar] = av0.z; As[acol + 3][ar] = av0.w;
        As[acol + 4][ar] = av1.x; As[acol + 5][ar] = av1.y;
        As[acol + 6][ar] = av1.z; As[acol + 7][ar] = av1.w;
        int br = tid >> 2;
        Bs[bcol + 0][br] = bv.x; Bs[bcol + 1][br] = bv.y;
        Bs[bcol + 2][br] = bv.z; Bs[bcol + 3][br] = bv.w;
        __syncthreads();
#pragma unroll
        for (int kk = 0; kk < 16; kk++) {
            ulonglong2 la = *(const ulonglong2*)&As[kk][ty * 8];
            ulonglong2 lb = *(const ulonglong2*)&As[kk][ty * 8 + 4];
            float4 bq = *(const float4*)&Bs[kk][tx * 4];
            unsigned long long am[4] = {la.x, la.y, lb.x, lb.y};
            unsigned long long bs[4] = {pk(bq.x, bq.x), pk(bq.y, bq.y),
                                        pk(bq.z, bq.z), pk(bq.w, bq.w)};
#pragma unroll
            for (int mp = 0; mp < 4; mp++)
#pragma unroll
                for (int n = 0; n < 4; n++)
                    cp[mp][n] = fma2(am[mp], bs[n], cp[mp][n]);
        }
        __syncthreads();
    }

    float4 b4 = *(const float4*)(bias + n0 + tx * 4);
#pragma unroll
    for (int mp = 0; mp < 4; mp++) {
        float lo[4], hi[4];
#pragma unroll
        for (int n = 0; n < 4; n++) upk(cp[mp][n], lo[n], hi[n]);
        float4 o0 = make_float4(lo[0] + b4.x, lo[1] + b4.y, lo[2] + b4.z, lo[3] + b4.w);
        float4 o1 = make_float4(hi[0] + b4.x, hi[1] + b4.y, hi[2] + b4.z, hi[3] + b4.w);
        if (RELU) {
            o0.x = fmaxf(o0.x, 0.f); o0.y = fmaxf(o0.y, 0.f);
            o0.z = fmaxf(o0.z, 0.f); o0.w = fmaxf(o0.w, 0.f);
            o1.x = fmaxf(o1.x, 0.f); o1.y = fmaxf(o1.y, 0.f);
            o1.z = fmaxf(o1.z, 0.f); o1.w = fmaxf(o1.w, 0.f);
        }
        int r0 = m0 + ty * 8 + mp * 2;
        if (r0 < M)     *(float4*)(C + (size_t)r0 * N + n0 + tx * 4) = o0;
        if (r0 + 1 < M) *(float4*)(C + (size_t)(r0 + 1) * N + n0 + tx * 4) = o1;
    }
}

// q = LN_ns(slots)@q_w^T + q_b ; hg = slots@gru_wh^T + gru_bh (22 rows)
__global__ void k_small(const float* __restrict__ slots,
                        const float* __restrict__ nsg, const float* __restrict__ nsb,
                        const float* __restrict__ qw, const float* __restrict__ qb,
                        const float* __restrict__ wh, const float* __restrict__ bh) {
    __shared__ float red[32];
    __shared__ float sraw[DD];
    __shared__ float sln[DD];
    int i = blockIdx.x, c = threadIdx.x;
    float x = slots[i * DD + c];
    sraw[c] = x;
    float mean = blockSum(x, red) * (1.f / 256.f);
    float d0 = x - mean;
    float var = blockSum(d0 * d0, red) * (1.f / 256.f);
    sln[c] = d0 * rsqrtf(var + 1e-5f) * nsg[c] + nsb[c];
    __syncthreads();
    float acc = qb[c];
    const float* wr = qw + (size_t)c * 256;
#pragma unroll 8
    for (int k = 0; k < 256; k++) acc += sln[k] * wr[k];
    g_qs[i * DD + c] = acc;
#pragma unroll
    for (int j = 0; j < 3; j++) {
        int u = j * 256 + c;
        float a = bh[u];
        const float* hr = wh + (size_t)u * 256;
#pragma unroll 8
        for (int k = 0; k < 256; k++) a += sraw[k] * hr[k];
        g_hg[i * 768 + u] = a;
    }
}

__device__ __forceinline__ void softmax_store(const unsigned long long* d,
                                              float* __restrict__ dst, int j) {
    float v[SS];
#pragma unroll
    for (int ip = 0; ip < 11; ip++) {
        float a, b;
        upk(d[ip], a, b);
        v[2 * ip] = a * 0.0625f;
        v[2 * ip + 1] = b * 0.0625f;
    }
    float mx = v[0];
#pragma unroll
    for (int i = 1; i < SS; i++) mx = fmaxf(mx, v[i]);
    float s = 0.f;
#pragma unroll
    for (int i = 0; i < SS; i++) { v[i] = __expf(v[i] - mx); s += v[i]; }
    float inv = 1.f / s;
#pragma unroll
    for (int i = 0; i < SS; i++) dst[i * NTOK + j] = v[i] * inv + 1e-8f;
}

__global__ void __launch_bounds__(384) k_attn(float* __restrict__ out_attn,
                                              const float* __restrict__ kk) {
    __shared__ unsigned long long q2[11 * 256];
    __shared__ float ks[8][768];
    int bB = blockIdx.x, tid = threadIdx.x;
    for (int idx = tid; idx < 11 * 256; idx += 384) {
        int ip = idx >> 8, k = idx & 255;
        q2[idx] = pk(g_qs[(2 * ip) * DD + k], g_qs[(2 * ip + 1) * DD + k]);
    }
    unsigned long long da[11], db[11];
#pragma unroll
    for (int ip = 0; ip < 11; ip++) { da[ip] = 0ULL; db[ip] = 0ULL; }
    size_t rowbase = (size_t)bB * NTOK;
    for (int kc = 0; kc < 256; kc += 8) {
#pragma unroll
        for (int rr = 0; rr < 2; rr++) {
            int r = tid + rr * 384;
            const float4* src = (const float4*)(kk + (rowbase + r) * 256 + kc);
            float4 v0 = src[0], v1 = src[1];
            ks[0][r] = v0.x; ks[1][r] = v0.y; ks[2][r] = v0.z; ks[3][r] = v0.w;
            ks[4][r] = v1.x; ks[5][r] = v1.y; ks[6][r] = v1.z; ks[7][r] = v1.w;
        }
        __syncthreads();
#pragma unroll
        for (int kl = 0; kl < 8; kl++) {
            int k = kc + kl;
            float kv0 = ks[kl][tid], kv1 = ks[kl][tid + 384];
            unsigned long long s0 = pk(kv0, kv0), s1 = pk(kv1, kv1);
#pragma unroll
            for (int ip = 0; ip < 11; ip++) {
                unsigned long long qv = q2[ip * 256 + k];
                da[ip] = fma2(qv, s0, da[ip]);
                db[ip] = fma2(qv, s1, db[ip]);
            }
        }
        __syncthreads();
    }
    int wi = bB / BATCH, bb = bB % BATCH;
    float* dst = out_attn + ((size_t)(bb * NWIN + wi)) * SS * NTOK;
    softmax_store(da, dst, tid);
    softmax_store(db, dst, tid + 384);
}

__global__ void __launch_bounds__(256) k_upd(const float* __restrict__ attn,
                                             const float* __restrict__ vv) {
    __shared__ float red[32];
    __shared__ float sinv[SS];
    __shared__ unsigned long long at2[11 * 64];
    int bB = blockIdx.x, tid = threadIdx.x;
    int wi = bB / BATCH, bb = bB % BATCH;
    const float* ab = attn + ((size_t)(bb * NWIN + wi)) * SS * NTOK;
    for (int i = 0; i < SS; i++) {
        float p = 0.f;
        for (int j = tid; j < NTOK; j += 256) p += ab[i * NTOK + j];
        float s = blockSum(p, red);
        if (tid == 0) sinv[i] = 1.f / s;
    }
    __syncthreads();
    unsigned long long acc[11];
#pragma unroll
    for (int ip = 0; ip < 11; ip++) acc[ip] = 0ULL;
    for (int j0 = 0; j0 < NTOK; j0 += 64) {
        for (int idx = tid; idx < 11 * 64; idx += 256) {
            int ip = idx >> 6, jj = idx & 63;
            at2[idx] = pk(ab[(2 * ip) * NTOK + j0 + jj],
                          ab[(2 * ip + 1) * NTOK + j0 + jj]);
        }
        __syncthreads();
        const float* vp = vv + ((size_t)bB * NTOK + j0) * 256 + tid;
#pragma unroll 4
        for (int jj = 0; jj < 64; jj++) {
            float v = vp[(size_t)jj * 256];
            unsigned long long sv = pk(v, v);
#pragma unroll
            for (int ip = 0; ip < 11; ip++)
                acc[ip] = fma2(at2[ip * 64 + jj], sv, acc[ip]);
        }
        __syncthreads();
    }
#pragma unroll
    for (int ip = 0; ip < 11; ip++) {
        float u0, u1;
        upk(acc[ip], u0, u1);
        g_upd[((size_t)bB * SS + 2 * ip) * DD + tid] = u0 * sinv[2 * ip];
        g_upd[((size_t)bB * SS + 2 * ip + 1) * DD + tid] = u1 * sinv[2 * ip + 1];
    }
}

__global__ void k_gate(const float* __restrict__ slots) {
    int m = blockIdx.x, c = threadIdx.x;
    int Bi = m / NAC, i = m % NAC;
    size_t row = (size_t)Bi * SS + i;
    float ir = g_xg[row * 768 + c];
    float iz = g_xg[row * 768 + 256 + c];
    float in_ = g_xg[row * 768 + 512 + c];
    float hr = g_hg[i * 768 + c];
    float hz = g_hg[i * 768 + 256 + c];
    float hn = g_hg[i * 768 + 512 + c];
    float h = slots[i * DD + c];
    float r = 1.f / (1.f + __expf(-(ir + hr)));
    float z = 1.f / (1.f + __expf(-(iz + hz)));
    float n = tanhf(in_ + r * hn);
    g_so[(size_t)m * DD + c] = (1.f - z) * n + z * h;
}

__global__ void k_final(float* __restrict__ out) {
    int m = blockIdx.x, c = threadIdx.x;
    int Bi = m / NAC, sl = m % NAC;
    int wi = Bi / BATCH, bb = Bi % BATCH;
    out[(((size_t)bb * NWIN + wi) * NAC + sl) * DD + c] =
        g_so[(size_t)m * DD + c] + g_t3[(size_t)m * DD + c];
}

extern "C" void kernel_launch(void* const* d_in, const int* in_sizes, int n_in,
                              void* d_out, int out_size) {
    const float* inputs = (const float*)d_in[0];
    const float* slots  = (const float*)d_in[1];
    const float* pe_w   = (const float*)d_in[2];
    const float* pe_b   = (const float*)d_in[3];
    const float* LN_g   = (const float*)d_in[4];
    const float* LN_b   = (const float*)d_in[5];
    const float* ni_g   = (const float*)d_in[6];
    const float* ni_b   = (const float*)d_in[7];
    const float* ns_g   = (const float*)d_in[8];
    const float* ns_b   = (const float*)d_in[9];
    const float* npf_g  = (const float*)d_in[10];
    const float* npf_b  = (const float*)d_in[11];
    const float* FC1_w  = (const float*)d_in[12];
    const float* FC1_b  = (const float*)d_in[13];
    const float* FC2_w  = (const float*)d_in[14];
    const float* FC2_b  = (const float*)d_in[15];
    const float* q_w    = (const float*)d_in[16];
    const float* q_b    = (const float*)d_in[17];
    const float* k_w    = (const float*)d_in[18];
    const float* k_b    = (const float*)d_in[19];
    const float* v_w    = (const float*)d_in[20];
    const float* v_b    = (const float*)d_in[21];
    const float* ff1_w  = (const float*)d_in[22];
    const float* ff1_b  = (const float*)d_in[23];
    const float* ff2_w  = (const float*)d_in[24];
    const float* ff2_b  = (const float*)d_in[25];
    const float* gru_wi = (const float*)d_in[26];
    const float* gru_wh = (const float*)d_in[27];
    const float* gru_bi = (const float*)d_in[28];
    const float* gru_bh = (const float*)d_in[29];

    float* out = (float*)d_out;
    float* out_attn = out + SLOTS_OUT_ELEMS;

    float *b0, *b1, *b2, *upd_, *xg_, *so_, *soln_, *t2_, *t3_;
    cudaGetSymbolAddress((void**)&b0, g_buf0);
    cudaGetSymbolAddress((void**)&b1, g_buf1);
    cudaGetSymbolAddress((void**)&b2, g_buf2);
    cudaGetSymbolAddress((void**)&upd_, g_upd);
    cudaGetSymbolAddress((void**)&xg_, g_xg);
    cudaGetSymbolAddress((void**)&so_, g_so);
    cudaGetSymbolAddress((void**)&soln_, g_soln);
    cudaGetSymbolAddress((void**)&t2_, g_t2);
    cudaGetSymbolAddress((void**)&t3_, g_t3);

    __nv_bfloat16 *w1h, *w1l, *w2h, *w2l, *wkh, *wkl, *wvh, *wvl;
    cudaGetSymbolAddress((void**)&w1h, g_w1h); cudaGetSymbolAddress((void**)&w1l, g_w1l);
    cudaGetSymbolAddress((void**)&w2h, g_w2h); cudaGetSymbolAddress((void**)&w2l, g_w2l);
    cudaGetSymbolAddress((void**)&wkh, g_wkh); cudaGetSymbolAddress((void**)&wkl, g_wkl);
    cudaGetSymbolAddress((void**)&wvh, g_wvh); cudaGetSymbolAddress((void**)&wvl, g_wvl);

    cudaFuncSetAttribute(k_mma<true>, cudaFuncAttributeMaxDynamicSharedMemorySize, MM_SMEM);
    cudaFuncSetAttribute(k_mma<false>, cudaFuncAttributeMaxDynamicSharedMemorySize, MM_SMEM);

    // split weights
    k_split<<<256, 256>>>(FC1_w, w1h, w1l, 65536);
    k_split<<<256, 256>>>(FC2_w, w2h, w2l, 65536);
    k_split<<<256, 256>>>(k_w, wkh, wkl, 65536);
    k_split<<<256, 256>>>(v_w, wvh, wvl, 65536);

    // positional embedding + gather + LN
    k_pe<<<NTOK, 256>>>(pe_w, pe_b);
    k_winln<<<MBIG, 256>>>(inputs, LN_g, LN_b);

    dim3 gBig(MBIG / 128, 2);
    // MLP: FC1 (relu) -> FC2 (tensor cores)
    k_mma<true><<<gBig, 256, MM_SMEM>>>(b0, w1h, w1l, FC1_b, b1, MBIG);
    k_mma<false><<<gBig, 256, MM_SMEM>>>(b1, w2h, w2l, FC2_b, b2, MBIG);

    // norm_input, K and V projections
    k_ln<<<MBIG, 256>>>(b2, b0, ni_g, ni_b);
    k_mma<false><<<gBig, 256, MM_SMEM>>>(b0, wkh, wkl, k_b, b1, MBIG);  // kk
    k_mma<false><<<gBig, 256, MM_SMEM>>>(b0, wvh, wvl, v_b, b2, MBIG);  // vv

    // batch-invariant q and hidden gates
    k_small<<<SS, 256>>>(slots, ns_g, ns_b, q_w, q_b, gru_wh, gru_bh);

    // dots + softmax-over-slots + EPS (writes attns output directly)
    k_attn<<<BWIN, 384>>>(out_attn, b1);

    // renorm + weighted update
    k_upd<<<BWIN, 256>>>(out_attn, b2);

    // GRU input gates GEMM: (4928x256)@(768x256)^T
    dim3 gGru((MGRU + 127) / 128, 12);
    k_gemm<false><<<gGru, 256>>>(upd_, gru_wi, gru_bi, xg_, MGRU, 768);

    // gates -> slots (first 20)
    k_gate<<<MSO, 256>>>(slots);

    // residual MLP
    k_ln<<<MSO, 256>>>(so_, soln_, npf_g, npf_b);
    dim3 gSo(MSO / 128, 4);
    k_gemm<true><<<gSo, 256>>>(soln_, ff1_w, ff1_b, t2_, MSO, 256);
    k_gemm<false><<<gSo, 256>>>(t2_, ff2_w, ff2_b, t3_, MSO, 256);

    // residual + permute into slots output
    k_final<<<MSO, 256>>>(out);
}